// round 17
// baseline (speedup 1.0000x reference)
#include <cuda_runtime.h>
#include <cuda_fp16.h>

// SpatialTransformer: out[b,c,d,h,w] = trilinear_sample(src[b,c], (w,h,d)+flow[b,:,d,h,w])
// align_corners=True normalization cancels; padding_mode='zeros'.
//
// R17: R16 + z-ring reuse. Each block processes NCH=2 consecutive z-chunks of
// TZ=8 using a 16-slot z-ring tile (slot = z & 15). Chunk 0 fills 15 slices,
// chunk 1 fills only its 8 NEW slices (ring slots overwritten held slices the
// new chunk cannot need). Fill traffic x0.77, blocks 2400 -> 1200.
// Ring tile 16x23x40 half2 = 58.9KB, 3 blocks x 512 = 48 warps (the proven
// sweet spot). Gather: local-frame x/y, global-frame z, HFMA2 zy-blend, lerp
// x-blend, vectorized fill for x-interior blocks.

#define Dz 160
#define Hy 192
#define Wx 160
#define Bn 2
#define HW (Hy * Wx)            // 30720
#define DHW (Dz * Hy * Wx)      // 4915200

#define RH 3                    // y/z halo radius
#define XHL 4                   // x halo (left/right) -> 16B-aligned rows
#define TX 32
#define TY 16
#define TZ 8
#define NCH 2                   // z-chunks per block
#define ZPB (TZ * NCH)          // 16 z-voxels per block
#define EX (TX + 2 * XHL)       // 40
#define EY (TY + 2 * RH + 1)    // 23
#define RING 16                 // z ring slots (power of 2)
#define EYEX (EY * EX)          // 920
#define ESZ (RING * EYEX)       // 14720
#define SMEM_BYTES (ESZ * (int)sizeof(__half2))  // 58880

#define NTHREADS 512
#define NWARPS (NTHREADS / 32)  // 16

__device__ __forceinline__ void fallback_gather(
    const float* c0, const float* c1,
    int x0, int y0, int z0,
    float fx, float fy, float fz,
    float& acc0, float& acc1)
{
    int x1 = x0 + 1, y1 = y0 + 1, z1 = z0 + 1;
    float wx0 = (x0 >= 0 && x0 < Wx) ? (1.0f - fx) : 0.0f;
    float wx1 = (x1 >= 0 && x1 < Wx) ? fx          : 0.0f;
    float wy0 = (y0 >= 0 && y0 < Hy) ? (1.0f - fy) : 0.0f;
    float wy1 = (y1 >= 0 && y1 < Hy) ? fy          : 0.0f;
    float wz0 = (z0 >= 0 && z0 < Dz) ? (1.0f - fz) : 0.0f;
    float wz1 = (z1 >= 0 && z1 < Dz) ? fz          : 0.0f;

    int x0c = min(max(x0, 0), Wx - 1);
    int x1c = min(max(x1, 0), Wx - 1);
    int y0c = min(max(y0, 0), Hy - 1);
    int y1c = min(max(y1, 0), Hy - 1);
    int z0c = min(max(z0, 0), Dz - 1);
    int z1c = min(max(z1, 0), Dz - 1);

    int zy00 = z0c * HW + y0c * Wx;
    int zy01 = z0c * HW + y1c * Wx;
    int zy10 = z1c * HW + y0c * Wx;
    int zy11 = z1c * HW + y1c * Wx;

    float w00 = wz0 * wy0, w01 = wz0 * wy1;
    float w10 = wz1 * wy0, w11 = wz1 * wy1;
    float w000 = w00 * wx0, w001 = w00 * wx1;
    float w010 = w01 * wx0, w011 = w01 * wx1;
    float w100 = w10 * wx0, w101 = w10 * wx1;
    float w110 = w11 * wx0, w111 = w11 * wx1;

    acc0  = w000 * __ldg(c0 + zy00 + x0c) + w001 * __ldg(c0 + zy00 + x1c);
    acc0 += w010 * __ldg(c0 + zy01 + x0c) + w011 * __ldg(c0 + zy01 + x1c);
    acc0 += w100 * __ldg(c0 + zy10 + x0c) + w101 * __ldg(c0 + zy10 + x1c);
    acc0 += w110 * __ldg(c0 + zy11 + x0c) + w111 * __ldg(c0 + zy11 + x1c);

    acc1  = w000 * __ldg(c1 + zy00 + x0c) + w001 * __ldg(c1 + zy00 + x1c);
    acc1 += w010 * __ldg(c1 + zy01 + x0c) + w011 * __ldg(c1 + zy01 + x1c);
    acc1 += w100 * __ldg(c1 + zy10 + x0c) + w101 * __ldg(c1 + zy10 + x1c);
    acc1 += w110 * __ldg(c1 + zy11 + x0c) + w111 * __ldg(c1 + zy11 + x1c);
}

// Fill ring slices [z_from, z_to] (inclusive, logical z; clamped for src reads).
__device__ __forceinline__ void fill_slices(
    __half2* __restrict__ tile,
    const float* __restrict__ c0,
    int x_org, int y_org, int z_from, int z_to,
    int lane, int warp, bool x_fast)
{
    int nsl = z_to - z_from + 1;
    int NR = nsl * EY;

    if (x_fast) {
        // 3 rows per warp-iteration, lanes 0-29 active, one float4 quad each.
        int row_off = lane / 10;
        int qi = lane - row_off * 10;
        bool active = lane < 30;
        int ngroups = (NR + 2) / 3;
        for (int t = warp; t < ngroups; t += NWARPS) {
            int row = t * 3 + row_off;
            if (active && row < NR) {
                int sl = row / EY;
                int ey = row - sl * EY;
                int zi = z_from + sl;
                int gz = min(max(zi, 0), Dz - 1);
                int gy = min(max(y_org + ey, 0), Hy - 1);
                int slot = zi & (RING - 1);
                const float* rbase = c0 + (gz * Hy + gy) * Wx + x_org;
                float4 a  = __ldg((const float4*)rbase + qi);
                float4 bb = __ldg((const float4*)(rbase + DHW) + qi);

                __half2 h0 = __floats2half2_rn(a.x, bb.x);
                __half2 h1 = __floats2half2_rn(a.y, bb.y);
                __half2 h2 = __floats2half2_rn(a.z, bb.z);
                __half2 h3 = __floats2half2_rn(a.w, bb.w);
                uint4 v;
                v.x = *reinterpret_cast<unsigned*>(&h0);
                v.y = *reinterpret_cast<unsigned*>(&h1);
                v.z = *reinterpret_cast<unsigned*>(&h2);
                v.w = *reinterpret_cast<unsigned*>(&h3);
                *reinterpret_cast<uint4*>(tile + slot * EYEX + ey * EX + qi * 4) = v;
            }
        }
    } else {
        // Scalar clamped fill: one row per warp-iteration, 40 elems (2 strips).
        for (int r = warp; r < NR; r += NWARPS) {
            int sl = r / EY;
            int ey = r - sl * EY;
            int zi = z_from + sl;
            int gz = min(max(zi, 0), Dz - 1);
            int gy = min(max(y_org + ey, 0), Hy - 1);
            int slot = zi & (RING - 1);
            const float* r0 = c0 + (gz * Hy + gy) * Wx;
            const float* r1 = r0 + DHW;
            __half2* trow = tile + slot * EYEX + ey * EX;

            int gx0 = min(max(x_org + lane, 0), Wx - 1);
            trow[lane] = __floats2half2_rn(__ldg(r0 + gx0), __ldg(r1 + gx0));
            int ex = lane + 32;
            if (ex < EX) {
                int gx1 = min(max(x_org + ex, 0), Wx - 1);
                trow[ex] = __floats2half2_rn(__ldg(r0 + gx1), __ldg(r1 + gx1));
            }
        }
    }
}

template <bool INTERIOR>
__device__ __forceinline__ void gather_chunk(
    const __half2* __restrict__ tile,
    const float* __restrict__ c0, const float* __restrict__ c1,
    const float* __restrict__ fb, float* __restrict__ ob,
    int lane, int warp, int zc, int x_org, int y_org)
{
    int w = x_org + XHL + lane;
    int h = y_org + RH + warp;
    int s_base = ((zc)*Hy + h) * Wx + w;

    float xbase = (float)(lane + XHL);
    float ybase = (float)(warp + RH);
    int zlo = zc - RH;

    #pragma unroll
    for (int kz = 0; kz < TZ; kz++) {
        int d = zc + kz;
        int s = s_base + kz * HW;

        float xl = xbase + __ldg(fb + s);
        float yl = ybase + __ldg(fb + s + DHW);
        float zl = (float)d + __ldg(fb + s + 2 * DHW);   // global-frame z

        float lxf = floorf(xl), lyf = floorf(yl), lzf = floorf(zl);
        float fx = xl - lxf, fy = yl - lyf, fz = zl - lzf;
        int lx = (int)lxf, ly = (int)lyf, lz = (int)lzf;

        float acc0, acc1;
        if ((unsigned)lx < (unsigned)(EX - 1) &&
            (unsigned)ly < (unsigned)(EY - 1) &&
            (unsigned)(lz - zlo) < (unsigned)(TZ + 2 * RH)) {
            float wy0, wy1, wz0, wz1;
            float wx0 = 0.0f, wx1 = 0.0f;   // edge path only
            if (INTERIOR) {
                wy0 = 1.0f - fy; wy1 = fy;
                wz0 = 1.0f - fz; wz1 = fz;
            } else {
                int x0 = lx + x_org, y0 = ly + y_org;
                wx0 = (x0 >= 0 && x0 < Wx)         ? (1.0f - fx) : 0.0f;
                wx1 = (x0 + 1 >= 0 && x0 + 1 < Wx) ? fx          : 0.0f;
                wy0 = (y0 >= 0 && y0 < Hy)         ? (1.0f - fy) : 0.0f;
                wy1 = (y0 + 1 >= 0 && y0 + 1 < Hy) ? fy          : 0.0f;
                wz0 = (lz >= 0 && lz < Dz)         ? (1.0f - fz) : 0.0f;
                wz1 = (lz + 1 >= 0 && lz + 1 < Dz) ? fz          : 0.0f;
            }

            __half2 hw00 = __float2half2_rn(wz0 * wy0);
            __half2 hw01 = __float2half2_rn(wz0 * wy1);
            __half2 hw10 = __float2half2_rn(wz1 * wy0);
            __half2 hw11 = __float2half2_rn(wz1 * wy1);

            const __half2* t00 = tile + (lz & (RING - 1)) * EYEX + ly * EX + lx;
            const __half2* t10 = tile + ((lz + 1) & (RING - 1)) * EYEX + ly * EX + lx;

            __half2 lo = __hmul2(hw00, t00[0]);
            lo = __hfma2(hw01, t00[EX],     lo);
            lo = __hfma2(hw10, t10[0],      lo);
            lo = __hfma2(hw11, t10[EX],     lo);
            __half2 hi = __hmul2(hw00, t00[1]);
            hi = __hfma2(hw01, t00[EX + 1], hi);
            hi = __hfma2(hw10, t10[1],      hi);
            hi = __hfma2(hw11, t10[EX + 1], hi);

            float2 flo = __half22float2(lo);
            float2 fhi = __half22float2(hi);

            if (INTERIOR) {
                acc0 = fmaf(fx, fhi.x - flo.x, flo.x);
                acc1 = fmaf(fx, fhi.y - flo.y, flo.y);
            } else {
                acc0 = wx0 * flo.x + wx1 * fhi.x;
                acc1 = wx0 * flo.y + wx1 * fhi.y;
            }
        } else {
            fallback_gather(c0, c1, lx + x_org, ly + y_org, lz,
                            fx, fy, fz, acc0, acc1);
        }

        ob[s] = acc0;
        ob[DHW + s] = acc1;
    }
}

__global__ __launch_bounds__(NTHREADS, 3) void warp3d_tiled(
    const float* __restrict__ src,
    const float* __restrict__ flow,
    float* __restrict__ out)
{
    extern __shared__ __half2 tile[];

    int bx = blockIdx.x;            // 0..4
    int by = blockIdx.y;            // 0..11
    int bzb = blockIdx.z;           // 0..(Dz/ZPB)*Bn-1 = 0..19
    int b  = bzb / (Dz / ZPB);
    int zg = bzb % (Dz / ZPB);
    int zbase = zg * ZPB;

    int x_org = bx * TX - XHL;      // multiple of 4
    int y_org = by * TY - RH;

    const float* c0 = src + (size_t)b * 2 * DHW;
    const float* c1 = c0 + DHW;
    const float* fb = flow + (size_t)b * 3 * DHW;
    float* ob = out + (size_t)b * 2 * DHW;

    int lane = threadIdx.x & 31;
    int warp = threadIdx.x >> 5;

    bool x_fast = (x_org >= 0) && (x_org + EX <= Wx);
    bool y_int  = (y_org >= 0) && (y_org + EY <= Hy);
    bool xy_int = x_fast && y_int;

    #pragma unroll
    for (int c = 0; c < NCH; c++) {
        int zc = zbase + c * TZ;
        int z_from = (c == 0) ? (zc - RH) : (zc + RH + 1);
        int z_to   = zc + TZ + RH;

        if (c > 0) __syncthreads();     // prior gather must finish before overwrite
        fill_slices(tile, c0, x_org, y_org, z_from, z_to, lane, warp, x_fast);
        __syncthreads();

        bool z_int = (zc >= RH) && (zc + TZ + RH <= Dz - 1);
        if (xy_int && z_int)
            gather_chunk<true>(tile, c0, c1, fb, ob, lane, warp, zc, x_org, y_org);
        else
            gather_chunk<false>(tile, c0, c1, fb, ob, lane, warp, zc, x_org, y_org);
    }
}

extern "C" void kernel_launch(void* const* d_in, const int* in_sizes, int n_in,
                              void* d_out, int out_size) {
    const float* src  = (const float*)d_in[0];
    const float* flow = (const float*)d_in[1];
    float* out = (float*)d_out;

    cudaFuncSetAttribute(warp3d_tiled,
                         cudaFuncAttributeMaxDynamicSharedMemorySize, SMEM_BYTES);

    dim3 grid(Wx / TX, Hy / TY, (Dz / ZPB) * Bn);
    warp3d_tiled<<<grid, NTHREADS, SMEM_BYTES>>>(src, flow, out);
}